// round 2
// baseline (speedup 1.0000x reference)
#include <cuda_runtime.h>
#include <cstddef>

#define NB 64
#define NK 64
#define ND 128

// Scratch (no allocation allowed in kernel_launch)
__device__ float g_M[NB * NK * ND];     // K*mask_c*concept + sum_j mask_n*neighbor
__device__ float g_coef[NB * NK];       // K*mask_c + cnt
__device__ float g_t[NB * ND];          // stu @ W1b + b1

// ---------------------------------------------------------------------------
// t[b][d] = sum_k stu[b][k] * W1[(128+k)*128 + d] + b1[d]
// ---------------------------------------------------------------------------
__global__ void k_stu(const float* __restrict__ stu, const float* __restrict__ W1,
                      const float* __restrict__ b1) {
    int b = blockIdx.x;
    int d = threadIdx.x;
    __shared__ float s[ND];
    s[d] = stu[b * ND + d];
    __syncthreads();
    float acc = b1[d];
#pragma unroll 16
    for (int k = 0; k < ND; k++)
        acc = fmaf(s[k], W1[(ND + k) * ND + d], acc);
    g_t[b * ND + d] = acc;
}

// ---------------------------------------------------------------------------
// Per (b,i): stream K=64 neighbor rows (128 floats each), mask = (row-sum != 0),
// masked-accumulate + count; fuse concept term. 8 warps x 8 rows, float4 loads.
// ---------------------------------------------------------------------------
__global__ void k_reduce(const float* __restrict__ neighbor,
                         const float* __restrict__ cpt) {
    int r = blockIdx.x;                 // r = b*K + i
    int tid = threadIdx.x;
    int w = tid >> 5;
    int lane = tid & 31;

    const float4* base = (const float4*)(neighbor + (size_t)r * NK * ND);

    // Load 8 rows per warp up front: 8 outstanding 512B loads per warp (MLP=8)
    float4 v[8];
#pragma unroll
    for (int j = 0; j < 8; j++)
        v[j] = base[(w * 8 + j) * (ND / 4) + lane];

    float4 acc = make_float4(0.f, 0.f, 0.f, 0.f);
    int cnt = 0;
#pragma unroll
    for (int j = 0; j < 8; j++) {
        float s = v[j].x + v[j].y + v[j].z + v[j].w;
#pragma unroll
        for (int o = 16; o; o >>= 1)
            s += __shfl_xor_sync(0xffffffffu, s, o);
        if (s != 0.0f) {
            acc.x += v[j].x; acc.y += v[j].y; acc.z += v[j].z; acc.w += v[j].w;
            cnt++;
        }
    }

    __shared__ float s_acc[8][ND];
    __shared__ int   s_cnt[8];
    __shared__ float s_csum;

    ((float4*)s_acc[w])[lane] = acc;
    if (lane == 0) s_cnt[w] = cnt;

    if (w == 0) {
        // concept-row sum for mask_c
        float4 c4 = ((const float4*)(cpt + (size_t)r * ND))[lane];
        float cs = c4.x + c4.y + c4.z + c4.w;
#pragma unroll
        for (int o = 16; o; o >>= 1)
            cs += __shfl_xor_sync(0xffffffffu, cs, o);
        if (lane == 0) s_csum = cs;
    }
    __syncthreads();

    if (tid < ND) {
        float a = 0.f;
#pragma unroll
        for (int ww = 0; ww < 8; ww++) a += s_acc[ww][tid];
        float mc = (s_csum != 0.0f) ? (float)NK : 0.0f;
        g_M[(size_t)r * ND + tid] = fmaf(mc, cpt[(size_t)r * ND + tid], a);
        if (tid == 0) {
            int c = 0;
#pragma unroll
            for (int ww = 0; ww < 8; ww++) c += s_cnt[ww];
            g_coef[r] = mc + (float)c;
        }
    }
}

// ---------------------------------------------------------------------------
// out[r][c] = 0.5 * ( sum_k M[r][k]*W1[k*128+c] + coef[r]*t[b][c] ),  b = r/64
// 64 blocks (one per b, 64 rows each), 256 threads, 8 rows x 4 cols per thread.
// ---------------------------------------------------------------------------
__global__ void __launch_bounds__(256) k_gemm(const float* __restrict__ W1,
                                              float* __restrict__ out) {
    int blk = blockIdx.x;                       // = b
    int tid = threadIdx.x;
    int c0 = (tid & 31) * 4;
    int rbase = blk * 64 + (tid >> 5) * 8;

    float acc[8][4];
#pragma unroll
    for (int rr = 0; rr < 8; rr++)
#pragma unroll
        for (int q = 0; q < 4; q++) acc[rr][q] = 0.f;

#pragma unroll 4
    for (int kk = 0; kk < ND; kk += 4) {
        float4 w0 = *(const float4*)&W1[(kk + 0) * ND + c0];
        float4 w1 = *(const float4*)&W1[(kk + 1) * ND + c0];
        float4 w2 = *(const float4*)&W1[(kk + 2) * ND + c0];
        float4 w3 = *(const float4*)&W1[(kk + 3) * ND + c0];
#pragma unroll
        for (int rr = 0; rr < 8; rr++) {
            float4 a = *(const float4*)&g_M[(size_t)(rbase + rr) * ND + kk];
            acc[rr][0] = fmaf(a.x, w0.x, fmaf(a.y, w1.x, fmaf(a.z, w2.x, fmaf(a.w, w3.x, acc[rr][0]))));
            acc[rr][1] = fmaf(a.x, w0.y, fmaf(a.y, w1.y, fmaf(a.z, w2.y, fmaf(a.w, w3.y, acc[rr][1]))));
            acc[rr][2] = fmaf(a.x, w0.z, fmaf(a.y, w1.z, fmaf(a.z, w2.z, fmaf(a.w, w3.z, acc[rr][2]))));
            acc[rr][3] = fmaf(a.x, w0.w, fmaf(a.y, w1.w, fmaf(a.z, w2.w, fmaf(a.w, w3.w, acc[rr][3]))));
        }
    }

    float4 tb = *(const float4*)&g_t[blk * ND + c0];
#pragma unroll
    for (int rr = 0; rr < 8; rr++) {
        float cf = g_coef[rbase + rr];
        float4 o;
        o.x = 0.5f * (acc[rr][0] + cf * tb.x);
        o.y = 0.5f * (acc[rr][1] + cf * tb.y);
        o.z = 0.5f * (acc[rr][2] + cf * tb.z);
        o.w = 0.5f * (acc[rr][3] + cf * tb.w);
        *(float4*)&out[(size_t)(rbase + rr) * ND + c0] = o;
    }
}

// ---------------------------------------------------------------------------
// Inputs (metadata order): stu_emb[64,128], concept_emb[64,64,128],
// neighbor_emb[64,64,64,128], W1[256,128], b1[128], Wn[256,1], bn[1]
// Output: float32 [64,64,128]
// ---------------------------------------------------------------------------
extern "C" void kernel_launch(void* const* d_in, const int* in_sizes, int n_in,
                              void* d_out, int out_size) {
    const float* stu      = (const float*)d_in[0];
    const float* cpt      = (const float*)d_in[1];
    const float* neighbor = (const float*)d_in[2];
    const float* W1       = (const float*)d_in[3];
    const float* b1       = (const float*)d_in[4];
    // d_in[5] (Wn), d_in[6] (bn) are dead: softmax over a size-1 axis == 1.0
    float* out = (float*)d_out;

    k_stu<<<NB, ND>>>(stu, W1, b1);
    k_reduce<<<NB * NK, 256>>>(neighbor, cpt);
    k_gemm<<<NB, 256>>>(W1, out);
}

// round 4
// speedup vs baseline: 1.3478x; 1.3478x over previous
#include <cuda_runtime.h>
#include <cstddef>

#define NB 64
#define NK 64
#define ND 128

// Scratch (no allocation allowed in kernel_launch)
__device__ float g_M[NB * NK * ND];     // K*mask_c*concept + sum_j mask_n*neighbor
__device__ float g_coef[NB * NK];       // K*mask_c + cnt

// ---------------------------------------------------------------------------
// Per (b,i): stream K=64 neighbor rows (128 floats each), mask = (row-sum != 0),
// masked-accumulate + count; fuse concept term. 8 warps x 8 rows, float4 loads.
// Streaming (.cs) loads: neighbor is read exactly once -> don't thrash L2,
// keep g_M / W1 resident for k_gemm.
// ---------------------------------------------------------------------------
__global__ void __launch_bounds__(256) k_reduce(const float* __restrict__ neighbor,
                                                const float* __restrict__ cpt) {
    int r = blockIdx.x;                 // r = b*K + i
    int tid = threadIdx.x;
    int w = tid >> 5;
    int lane = tid & 31;

    const float4* base = (const float4*)(neighbor + (size_t)r * NK * ND);

    // Load 8 rows per warp up front: 8 outstanding 512B loads per warp (MLP=8)
    float4 v[8];
#pragma unroll
    for (int j = 0; j < 8; j++)
        v[j] = __ldcs(&base[(w * 8 + j) * (ND / 4) + lane]);

    float4 acc = make_float4(0.f, 0.f, 0.f, 0.f);
    int cnt = 0;
#pragma unroll
    for (int j = 0; j < 8; j++) {
        float s = v[j].x + v[j].y + v[j].z + v[j].w;
#pragma unroll
        for (int o = 16; o; o >>= 1)
            s += __shfl_xor_sync(0xffffffffu, s, o);
        if (s != 0.0f) {
            acc.x += v[j].x; acc.y += v[j].y; acc.z += v[j].z; acc.w += v[j].w;
            cnt++;
        }
    }

    __shared__ float s_acc[8][ND];
    __shared__ int   s_cnt[8];
    __shared__ float s_csum;

    ((float4*)s_acc[w])[lane] = acc;
    if (lane == 0) s_cnt[w] = cnt;

    if (w == 0) {
        // concept-row sum for mask_c
        float4 c4 = ((const float4*)(cpt + (size_t)r * ND))[lane];
        float cs = c4.x + c4.y + c4.z + c4.w;
#pragma unroll
        for (int o = 16; o; o >>= 1)
            cs += __shfl_xor_sync(0xffffffffu, cs, o);
        if (lane == 0) s_csum = cs;
    }
    __syncthreads();

    if (tid < ND) {
        float a = 0.f;
#pragma unroll
        for (int ww = 0; ww < 8; ww++) a += s_acc[ww][tid];
        float mc = (s_csum != 0.0f) ? (float)NK : 0.0f;
        g_M[(size_t)r * ND + tid] = fmaf(mc, cpt[(size_t)r * ND + tid], a);
        if (tid == 0) {
            int c = 0;
#pragma unroll
            for (int ww = 0; ww < 8; ww++) c += s_cnt[ww];
            g_coef[r] = mc + (float)c;
        }
    }
}

// ---------------------------------------------------------------------------
// Fused: t[b] = stu[b] @ W1b + b1 (computed per-block, trivial), then
// out[r][c] = 0.5 * ( sum_k M[r][k]*W1[k*128+c] + coef[r]*t[b][c] )
// 256 blocks (16 rows each, one b per 4 blocks), 256 threads,
// 2 rows x 4 cols per thread.
// ---------------------------------------------------------------------------
__global__ void __launch_bounds__(256) k_gemm(const float* __restrict__ stu,
                                              const float* __restrict__ W1,
                                              const float* __restrict__ b1,
                                              float* __restrict__ out) {
    int blk = blockIdx.x;
    int b = blk >> 2;                    // 4 blocks per batch element
    int rbase = blk * 16;
    int tid = threadIdx.x;

    __shared__ float s_stu[ND];
    __shared__ float s_p[256];
    __shared__ float s_t[ND];

    if (tid < ND) s_stu[tid] = stu[b * ND + tid];
    __syncthreads();

    // t[b][col] = sum_k stu[b][k]*W1[(128+k)*128+col] + b1[col]
    // split k-range across two half-groups of threads
    {
        int col = tid & (ND - 1);
        int kh = tid >> 7;               // 0 or 1
        float a = 0.f;
        int k0 = kh * 64;
#pragma unroll 16
        for (int k = 0; k < 64; k++)
            a = fmaf(s_stu[k0 + k], W1[(ND + k0 + k) * ND + col], a);
        s_p[tid] = a;
    }
    __syncthreads();
    if (tid < ND) s_t[tid] = s_p[tid] + s_p[ND + tid] + b1[tid];
    __syncthreads();

    // main GEMM: rows rbase + rg*2 + {0,1}, cols c0..c0+3
    int c0 = (tid & 31) * 4;
    int rg = tid >> 5;                   // 0..7
    int r0 = rbase + rg * 2;

    float acc[2][4];
#pragma unroll
    for (int rr = 0; rr < 2; rr++)
#pragma unroll
        for (int q = 0; q < 4; q++) acc[rr][q] = 0.f;

#pragma unroll 4
    for (int kk = 0; kk < ND; kk += 4) {
        float4 w0 = *(const float4*)&W1[(kk + 0) * ND + c0];
        float4 w1 = *(const float4*)&W1[(kk + 1) * ND + c0];
        float4 w2 = *(const float4*)&W1[(kk + 2) * ND + c0];
        float4 w3 = *(const float4*)&W1[(kk + 3) * ND + c0];
#pragma unroll
        for (int rr = 0; rr < 2; rr++) {
            float4 a = *(const float4*)&g_M[(size_t)(r0 + rr) * ND + kk];
            acc[rr][0] = fmaf(a.x, w0.x, fmaf(a.y, w1.x, fmaf(a.z, w2.x, fmaf(a.w, w3.x, acc[rr][0]))));
            acc[rr][1] = fmaf(a.x, w0.y, fmaf(a.y, w1.y, fmaf(a.z, w2.y, fmaf(a.w, w3.y, acc[rr][1]))));
            acc[rr][2] = fmaf(a.x, w0.z, fmaf(a.y, w1.z, fmaf(a.z, w2.z, fmaf(a.w, w3.z, acc[rr][2]))));
            acc[rr][3] = fmaf(a.x, w0.w, fmaf(a.y, w1.w, fmaf(a.z, w2.w, fmaf(a.w, w3.w, acc[rr][3]))));
        }
    }

    float4 tb = *(const float4*)&s_t[c0];
#pragma unroll
    for (int rr = 0; rr < 2; rr++) {
        float cf = g_coef[r0 + rr];
        float4 o;
        o.x = 0.5f * (acc[rr][0] + cf * tb.x);
        o.y = 0.5f * (acc[rr][1] + cf * tb.y);
        o.z = 0.5f * (acc[rr][2] + cf * tb.z);
        o.w = 0.5f * (acc[rr][3] + cf * tb.w);
        *(float4*)&out[(size_t)(r0 + rr) * ND + c0] = o;
    }
}

// ---------------------------------------------------------------------------
// Inputs (metadata order): stu_emb[64,128], concept_emb[64,64,128],
// neighbor_emb[64,64,64,128], W1[256,128], b1[128], Wn[256,1], bn[1]
// Output: float32 [64,64,128]
// ---------------------------------------------------------------------------
extern "C" void kernel_launch(void* const* d_in, const int* in_sizes, int n_in,
                              void* d_out, int out_size) {
    const float* stu      = (const float*)d_in[0];
    const float* cpt      = (const float*)d_in[1];
    const float* neighbor = (const float*)d_in[2];
    const float* W1       = (const float*)d_in[3];
    const float* b1       = (const float*)d_in[4];
    // d_in[5] (Wn), d_in[6] (bn) are dead: softmax over a size-1 axis == 1.0
    float* out = (float*)d_out;

    k_reduce<<<NB * NK, 256>>>(neighbor, cpt);
    k_gemm<<<NB * 4, 256>>>(stu, W1, b1, out);
}